// round 2
// baseline (speedup 1.0000x reference)
#include <cuda_runtime.h>
#include <cstddef>

// Problem constants (fixed by reference)
#define NB   8
#define NQ   100
#define SH   128
#define SW   128
#define OH   512
#define OW   512

__device__ __forceinline__ float fast_tanh(float x) {
    float r;
    asm("tanh.approx.f32 %0, %1;" : "=f"(r) : "f"(x));
    return r;
}

// Grid: (128 row-blocks, 8 batches). Block: 512 threads (one per output column).
// Each thread produces 4 output rows (phases 0..3 of its row block) x 2 classes.
__global__ __launch_bounds__(512, 2)
void m2f_fused_kernel(const float* __restrict__ cls,
                      const float* __restrict__ masks,
                      float* __restrict__ out)
{
    const int k = blockIdx.x;   // source row index / output row-block (0..127)
    const int b = blockIdx.y;   // batch
    const int t = threadIdx.x;  // output column x (0..511)

    __shared__ float2 wts[NQ];             // class-0/1 softmax weights per query
    __shared__ float  buf[2][3][SW];       // double-buffered 3 source rows

    // --- per-CTA class softmax (classes 0,1 of 3) ---
    if (t < NQ) {
        const float* p = cls + ((size_t)b * NQ + t) * 3;
        float x0 = p[0], x1 = p[1], x2 = p[2];
        float m  = fmaxf(x0, fmaxf(x1, x2));
        float e0 = __expf(x0 - m), e1 = __expf(x1 - m), e2 = __expf(x2 - m);
        float inv = 1.0f / (e0 + e1 + e2);
        wts[t] = make_float2(e0 * inv, e1 * inv);
    }

    // clamped source rows for this row-block
    const int r0 = (k == 0)      ? 0        : (k - 1);
    const int r1 = k;
    const int r2 = (k == SH - 1) ? (SH - 1) : (k + 1);

    const float* mb = masks + (size_t)b * NQ * SH * SW;

    // stage q = 0 into buf[0]  (96 threads x float4 = 3 rows x 128 floats)
    int stg_row = 0, stg_c4 = 0;
    const float4* stg_src0 = nullptr;
    bool stager = (t < 96);
    if (stager) {
        int rr = t >> 5;            // 0..2
        stg_c4  = t & 31;           // 0..31 (float4 index)
        stg_row = (rr == 0) ? r0 : ((rr == 1) ? r1 : r2);
        stg_src0 = reinterpret_cast<const float4*>(mb + (size_t)stg_row * SW);
        float4 v = __ldg(&stg_src0[stg_c4]);
        reinterpret_cast<float4*>(&buf[0][rr][0])[stg_c4] = v;
    }

    // per-thread horizontal geometry
    const int kx = t >> 2;
    const int px = t & 3;
    int cL, cR; float fx;
    if (px < 2) { cL = (kx == 0) ? 0 : kx - 1; cR = kx;
                  fx = (px == 0) ? 0.625f : 0.875f; }
    else        { cL = kx; cR = (kx == SW - 1) ? (SW - 1) : kx + 1;
                  fx = (px == 2) ? 0.125f : 0.375f; }

    float acc0[4] = {0.f, 0.f, 0.f, 0.f};
    float acc1[4] = {0.f, 0.f, 0.f, 0.f};

    const size_t qstride = (size_t)SH * SW;

    #pragma unroll 1
    for (int q = 0; q < NQ; q++) {
        __syncthreads();                   // buf[q&1] ready; buf[(q+1)&1] free
        const int s = q & 1;

        // prefetch next tile into registers (hides LDG behind compute)
        float4 vnext;
        bool do_stage = stager && (q + 1 < NQ);
        if (do_stage) {
            const float4* src = reinterpret_cast<const float4*>(
                mb + (size_t)(q + 1) * qstride + (size_t)stg_row * SW);
            vnext = __ldg(&src[stg_c4]);
        }

        const float2 w = wts[q];
        const float a0 = buf[s][0][cL], a1 = buf[s][0][cR];
        const float b0 = buf[s][1][cL], b1 = buf[s][1][cR];
        const float c0 = buf[s][2][cL], c1 = buf[s][2][cR];

        const float d1L = b0 - a0, d1R = b1 - a1;
        const float d2L = c0 - b0, d2R = c1 - b1;

        float vL[4], vR[4];
        vL[0] = fmaf(0.625f, d1L, a0);  vR[0] = fmaf(0.625f, d1R, a1);
        vL[1] = fmaf(0.875f, d1L, a0);  vR[1] = fmaf(0.875f, d1R, a1);
        vL[2] = fmaf(0.125f, d2L, b0);  vR[2] = fmaf(0.125f, d2R, b1);
        vL[3] = fmaf(0.375f, d2L, b0);  vR[3] = fmaf(0.375f, d2R, b1);

        #pragma unroll
        for (int p = 0; p < 4; p++) {
            float h  = fmaf(fx, vR[p] - vL[p], vL[p]);
            float th = fast_tanh(0.5f * h);
            float sg = fmaf(th, 0.5f, 0.5f);     // sigmoid(h)
            acc0[p] = fmaf(w.x, sg, acc0[p]);
            acc1[p] = fmaf(w.y, sg, acc1[p]);
        }

        if (do_stage) {
            int rr = t >> 5;
            reinterpret_cast<float4*>(&buf[s ^ 1][rr][0])[stg_c4] = vnext;
        }
    }

    // write results: out[b][c][4k+p][t]
    #pragma unroll
    for (int p = 0; p < 4; p++) {
        const int y = 4 * k + p;
        out[(((size_t)b * 2 + 0) * OH + y) * OW + t] = acc0[p];
        out[(((size_t)b * 2 + 1) * OH + y) * OW + t] = acc1[p];
    }
}

extern "C" void kernel_launch(void* const* d_in, const int* in_sizes, int n_in,
                              void* d_out, int out_size)
{
    const float* cls   = (const float*)d_in[0];  // [8,100,3]
    const float* masks = (const float*)d_in[1];  // [8,100,128,128]
    float*       out   = (float*)d_out;          // [8,2,512,512]

    dim3 grid(SH, NB);   // 128 row-blocks x 8 batches
    dim3 block(512);
    m2f_fused_kernel<<<grid, block>>>(cls, masks, out);
}

// round 5
// speedup vs baseline: 1.1044x; 1.1044x over previous
#include <cuda_runtime.h>
#include <cstddef>

#define NB   8
#define NQ   100
#define SH   128
#define SW   128
#define OH   512
#define OW   512

__device__ __forceinline__ float fast_tanh(float x) {
    float r;
    asm("tanh.approx.f32 %0, %1;" : "=f"(r) : "f"(x));
    return r;
}

// Grid: (128 row-blocks k, 8 batches). Block: 512 threads.
// Two-stage per query:
//   vertical: thread = (row-phase p, source col) -> one lerp into vrow[4][128]
//   horizontal: thread = (x-block kx, row-phase p) -> 4 consecutive output x
// Data pre-halved at staging; weights pre-halved; +Sum(w/2) folded at the end.
__global__ __launch_bounds__(512, 2)
void m2f_fused_kernel(const float* __restrict__ cls,
                      const float* __restrict__ masks,
                      float* __restrict__ out)
{
    const int k = blockIdx.x;
    const int b = blockIdx.y;
    const int t = threadIdx.x;

    // NOTE: buf is accessed via float4 — MUST be 16B aligned (R3/R4 fault:
    // it landed at smem offset 808 without the explicit alignment).
    __shared__ __align__(16) float buf[2][3][SW];  // double-buffered, pre-halved rows
    __shared__ __align__(16) float vrow[4][SW];    // vertical-lerp results (halved)
    __shared__ float2 wts[NQ];        // pre-halved class-0/1 weights
    __shared__ float2 wsum;           // sum of halved weights

    // ---- per-CTA class softmax (halved) ----
    if (t < NQ) {
        const float* p = cls + ((size_t)b * NQ + t) * 3;
        float x0 = p[0], x1 = p[1], x2 = p[2];
        float m  = fmaxf(x0, fmaxf(x1, x2));
        float e0 = __expf(x0 - m), e1 = __expf(x1 - m), e2 = __expf(x2 - m);
        float inv = 0.5f / (e0 + e1 + e2);
        wts[t] = make_float2(e0 * inv, e1 * inv);
    }

    // clamped source rows
    const int r0 = (k == 0)      ? 0        : (k - 1);
    const int r2 = (k == SH - 1) ? (SH - 1) : (k + 1);
    const float* mb = masks + (size_t)b * NQ * SH * SW;
    const size_t qstride = (size_t)SH * SW;

    // staging role: 96 threads x float4 cover 3 rows x 128 floats
    const bool stager = (t < 96);
    const int  rr     = t >> 5;           // 0..2
    const int  c4     = t & 31;           // float4 index
    const int  stg_row = (rr == 0) ? r0 : ((rr == 1) ? k : r2);
    const float* stg_base = mb + (size_t)stg_row * SW;

    if (stager) {
        float4 v = __ldg(reinterpret_cast<const float4*>(stg_base) + c4);
        v.x *= 0.5f; v.y *= 0.5f; v.z *= 0.5f; v.w *= 0.5f;
        reinterpret_cast<float4*>(&buf[0][rr][0])[c4] = v;
    }

    // vertical role: p = t>>7 (0..3), col = t&127
    const int vp   = t >> 7;
    const int vcol = t & 127;
    const int ra   = (vp < 2) ? 0 : 1;
    const int rb   = ra + 1;
    const float vf = (vp == 0) ? 0.625f : (vp == 1) ? 0.875f
                   : (vp == 2) ? 0.125f : 0.375f;

    // horizontal role: kx = t&127, row-phase ph = t>>7; outputs x = 4kx+0..3
    const int kx  = t & 127;
    const int ph  = t >> 7;
    const int kxm = (kx == 0)      ? 0        : kx - 1;
    const int kxp = (kx == SW - 1) ? (SW - 1) : kx + 1;

    __syncthreads();   // wts + buf[0] visible

    // weight sum (halved) reduced by warp 0
    if (t < 32) {
        float sx = 0.f, sy = 0.f;
        for (int q = t; q < NQ; q += 32) { sx += wts[q].x; sy += wts[q].y; }
        #pragma unroll
        for (int o = 16; o > 0; o >>= 1) {
            sx += __shfl_down_sync(0xFFFFFFFFu, sx, o);
            sy += __shfl_down_sync(0xFFFFFFFFu, sy, o);
        }
        if (t == 0) wsum = make_float2(sx, sy);
    }

    float acc0[4] = {0.f,0.f,0.f,0.f};   // class 0, x phases 0..3
    float acc1[4] = {0.f,0.f,0.f,0.f};   // class 1

    #pragma unroll 1
    for (int q = 0; q < NQ; q++) {
        const int s = q & 1;
        __syncthreads();   // buf[s] staged; vrow free

        // prefetch next tile (hide LDG under both stages)
        float4 vn;
        const bool ds = stager && (q + 1 < NQ);
        if (ds) {
            vn = __ldg(reinterpret_cast<const float4*>(
                           stg_base + (size_t)(q + 1) * qstride) + c4);
        }

        // vertical lerp: one value per thread
        {
            float a  = buf[s][ra][vcol];
            float bb = buf[s][rb][vcol];
            vrow[vp][vcol] = fmaf(vf, bb - a, a);
        }
        __syncthreads();   // vrow ready; buf[s^1] free for staging

        const float2 w  = wts[q];
        const float  vL = vrow[ph][kxm];
        const float  vM = vrow[ph][kx];
        const float  vR = vrow[ph][kxp];
        const float  dl = vM - vL;
        const float  dr = vR - vM;

        float h0 = fmaf(0.625f, dl, vL);
        float h1 = fmaf(0.875f, dl, vL);
        float h2 = fmaf(0.125f, dr, vM);
        float h3 = fmaf(0.375f, dr, vM);

        float t0 = fast_tanh(h0);
        float t1 = fast_tanh(h1);
        float t2 = fast_tanh(h2);
        float t3 = fast_tanh(h3);

        acc0[0] = fmaf(w.x, t0, acc0[0]);
        acc0[1] = fmaf(w.x, t1, acc0[1]);
        acc0[2] = fmaf(w.x, t2, acc0[2]);
        acc0[3] = fmaf(w.x, t3, acc0[3]);
        acc1[0] = fmaf(w.y, t0, acc1[0]);
        acc1[1] = fmaf(w.y, t1, acc1[1]);
        acc1[2] = fmaf(w.y, t2, acc1[2]);
        acc1[3] = fmaf(w.y, t3, acc1[3]);

        if (ds) {
            vn.x *= 0.5f; vn.y *= 0.5f; vn.z *= 0.5f; vn.w *= 0.5f;
            reinterpret_cast<float4*>(&buf[s ^ 1][rr][0])[c4] = vn;
        }
    }

    // out[b][c][4k+ph][4kx + 0..3] = acc + Sum(w/2)
    // d_out is cudaMalloc'd (256B-aligned); offsets are multiples of 4 floats
    // -> float4 stores are safe.
    const float2 S = wsum;
    const int y = 4 * k + ph;
    float4 o0 = make_float4(acc0[0] + S.x, acc0[1] + S.x,
                            acc0[2] + S.x, acc0[3] + S.x);
    float4 o1 = make_float4(acc1[0] + S.y, acc1[1] + S.y,
                            acc1[2] + S.y, acc1[3] + S.y);
    const size_t base0 = (((size_t)b * 2 + 0) * OH + y) * OW + 4 * kx;
    const size_t base1 = (((size_t)b * 2 + 1) * OH + y) * OW + 4 * kx;
    *reinterpret_cast<float4*>(out + base0) = o0;
    *reinterpret_cast<float4*>(out + base1) = o1;
}

extern "C" void kernel_launch(void* const* d_in, const int* in_sizes, int n_in,
                              void* d_out, int out_size)
{
    const float* cls   = (const float*)d_in[0];  // [8,100,3]
    const float* masks = (const float*)d_in[1];  // [8,100,128,128]
    float*       out   = (float*)d_out;          // [8,2,512,512]

    dim3 grid(SH, NB);
    dim3 block(512);
    m2f_fused_kernel<<<grid, block>>>(cls, masks, out);
}

// round 6
// speedup vs baseline: 1.4281x; 1.2931x over previous
#include <cuda_runtime.h>
#include <cstddef>

#define NB   8
#define NQ   100
#define SH   128
#define SW   128
#define OH   512
#define OW   512

__device__ __forceinline__ float fast_tanh(float x) {
    float r;
    asm("tanh.approx.f32 %0, %1;" : "=f"(r) : "f"(x));
    return r;
}

// Grid: (128 row-blocks k, 8 batches). Block: 512 threads, 3 CTAs/SM (full occ).
// Query-PAIR loop: 4-slot staging ring, one sync-pair per 2 queries.
//   vertical:   thread = (row-phase vp, source col) -> lerp for BOTH queries
//   horizontal: thread = (x-block kx, row-phase ph) -> 4 output x, both queries
// Data pre-halved at staging; weights pre-halved; +Sum(w/2) folded at the end.
__global__ __launch_bounds__(512, 3)
void m2f_fused_kernel(const float* __restrict__ cls,
                      const float* __restrict__ masks,
                      float* __restrict__ out)
{
    const int k = blockIdx.x;
    const int b = blockIdx.y;
    const int t = threadIdx.x;

    __shared__ __align__(16) float buf[4][3][SW];   // 4-slot ring, pre-halved rows
    __shared__ __align__(16) float vrow[2][4][SW];  // vertical lerps, 2 queries
    __shared__ float2 wts[NQ];
    __shared__ float2 wsum;

    // ---- per-CTA class softmax (halved) ----
    if (t < NQ) {
        const float* p = cls + ((size_t)b * NQ + t) * 3;
        float x0 = p[0], x1 = p[1], x2 = p[2];
        float m  = fmaxf(x0, fmaxf(x1, x2));
        float e0 = __expf(x0 - m), e1 = __expf(x1 - m), e2 = __expf(x2 - m);
        float inv = 0.5f / (e0 + e1 + e2);
        wts[t] = make_float2(e0 * inv, e1 * inv);
    }

    // clamped source rows
    const int r0 = (k == 0)      ? 0        : (k - 1);
    const int r2 = (k == SH - 1) ? (SH - 1) : (k + 1);
    const float* mb = masks + (size_t)b * NQ * SH * SW;
    const size_t qstride = (size_t)SH * SW;

    // staging role: 192 threads, each ONE float4; covers 2 queries x 3 rows x 128 f
    const bool stager = (t < 192);
    const int  qoff   = (t >= 96) ? 1 : 0;      // which query of the pair
    const int  rr     = (t % 96) >> 5;          // 0..2
    const int  c4     = t & 31;                 // float4 index
    const int  stg_row = (rr == 0) ? r0 : ((rr == 1) ? k : r2);
    // pointer to this stager's float4 for query (2j + qoff); advances 2q per pair
    const float4* pf = reinterpret_cast<const float4*>(
        mb + (size_t)qoff * qstride + (size_t)stg_row * SW) + c4;

    if (stager) {   // stage queries 0,1 into slots 0,1
        float4 v = __ldg(pf);
        v.x *= 0.5f; v.y *= 0.5f; v.z *= 0.5f; v.w *= 0.5f;
        reinterpret_cast<float4*>(&buf[qoff][rr][0])[c4] = v;
        pf += (2 * qstride) / 4;   // -> queries 2,3
    }

    // vertical role
    const int vp   = t >> 7;
    const int vcol = t & 127;
    const int ra   = (vp < 2) ? 0 : 1;
    const int rb   = ra + 1;
    const float vf = (vp == 0) ? 0.625f : (vp == 1) ? 0.875f
                   : (vp == 2) ? 0.125f : 0.375f;

    // horizontal role
    const int kx  = t & 127;
    const int ph  = t >> 7;
    const int kxm = (kx == 0)      ? 0        : kx - 1;
    const int kxp = (kx == SW - 1) ? (SW - 1) : kx + 1;

    __syncthreads();   // wts visible (buf[0..1] covered by loop sync)

    // weight sum (halved) reduced by warp 0
    if (t < 32) {
        float sx = 0.f, sy = 0.f;
        for (int q = t; q < NQ; q += 32) { sx += wts[q].x; sy += wts[q].y; }
        #pragma unroll
        for (int o = 16; o > 0; o >>= 1) {
            sx += __shfl_down_sync(0xFFFFFFFFu, sx, o);
            sy += __shfl_down_sync(0xFFFFFFFFu, sy, o);
        }
        if (t == 0) wsum = make_float2(sx, sy);
    }

    float acc0[4] = {0.f,0.f,0.f,0.f};
    float acc1[4] = {0.f,0.f,0.f,0.f};

    #pragma unroll 1
    for (int j = 0; j < NQ / 2; j++) {
        const int base = (j & 1) << 1;          // 0 or 2
        __syncthreads();   // slots base,base+1 staged; vrow free

        // prefetch next pair (one float4 per stager)
        float4 vn;
        const bool ds = stager && (j + 1 < NQ / 2);
        if (ds) vn = __ldg(pf);

        // vertical lerp for both queries of the pair
        {
            float a0 = buf[base    ][ra][vcol];
            float b0 = buf[base    ][rb][vcol];
            float a1 = buf[base + 1][ra][vcol];
            float b1 = buf[base + 1][rb][vcol];
            vrow[0][vp][vcol] = fmaf(vf, b0 - a0, a0);
            vrow[1][vp][vcol] = fmaf(vf, b1 - a1, a1);
        }
        __syncthreads();   // vrow ready; slots base^2 free for staging

        #pragma unroll
        for (int e = 0; e < 2; e++) {
            const float2 w  = wts[2 * j + e];
            const float  vL = vrow[e][ph][kxm];
            const float  vM = vrow[e][ph][kx];
            const float  vR = vrow[e][ph][kxp];
            const float  dl = vM - vL;
            const float  dr = vR - vM;

            float t0 = fast_tanh(fmaf(0.625f, dl, vL));
            float t1 = fast_tanh(fmaf(0.875f, dl, vL));
            float t2 = fast_tanh(fmaf(0.125f, dr, vM));
            float t3 = fast_tanh(fmaf(0.375f, dr, vM));

            acc0[0] = fmaf(w.x, t0, acc0[0]);
            acc0[1] = fmaf(w.x, t1, acc0[1]);
            acc0[2] = fmaf(w.x, t2, acc0[2]);
            acc0[3] = fmaf(w.x, t3, acc0[3]);
            acc1[0] = fmaf(w.y, t0, acc1[0]);
            acc1[1] = fmaf(w.y, t1, acc1[1]);
            acc1[2] = fmaf(w.y, t2, acc1[2]);
            acc1[3] = fmaf(w.y, t3, acc1[3]);
        }

        if (ds) {
            vn.x *= 0.5f; vn.y *= 0.5f; vn.z *= 0.5f; vn.w *= 0.5f;
            reinterpret_cast<float4*>(&buf[(base ^ 2) + qoff][rr][0])[c4] = vn;
            pf += (2 * qstride) / 4;
        }
    }

    // out[b][c][4k+ph][4kx + 0..3] = acc + Sum(w/2)
    const float2 S = wsum;
    const int y = 4 * k + ph;
    float4 o0 = make_float4(acc0[0] + S.x, acc0[1] + S.x,
                            acc0[2] + S.x, acc0[3] + S.x);
    float4 o1 = make_float4(acc1[0] + S.y, acc1[1] + S.y,
                            acc1[2] + S.y, acc1[3] + S.y);
    const size_t base0 = (((size_t)b * 2 + 0) * OH + y) * OW + 4 * kx;
    const size_t base1 = (((size_t)b * 2 + 1) * OH + y) * OW + 4 * kx;
    *reinterpret_cast<float4*>(out + base0) = o0;
    *reinterpret_cast<float4*>(out + base1) = o1;
}

extern "C" void kernel_launch(void* const* d_in, const int* in_sizes, int n_in,
                              void* d_out, int out_size)
{
    const float* cls   = (const float*)d_in[0];  // [8,100,3]
    const float* masks = (const float*)d_in[1];  // [8,100,128,128]
    float*       out   = (float*)d_out;          // [8,2,512,512]

    dim3 grid(SH, NB);
    dim3 block(512);
    m2f_fused_kernel<<<grid, block>>>(cls, masks, out);
}

// round 7
// speedup vs baseline: 1.5888x; 1.1125x over previous
#include <cuda_runtime.h>
#include <cstddef>

#define NB   8
#define NQ   100
#define SH   128
#define SW   128
#define OH   512
#define OW   512
#define QPI  4            // queries per iteration
#define NIT  (NQ / QPI)   // 25

__device__ __forceinline__ float fast_tanh(float x) {
    float r;
    asm("tanh.approx.f32 %0, %1;" : "=f"(r) : "f"(x));
    return r;
}

// Grid: (128 row-blocks k, 8 batches). Block: 512 threads, 3 CTAs/SM.
// Quad-query software pipeline, ONE __syncthreads per iteration:
//   iter j: horizontal(quad j, vrow[j&1]) || vertical(quad j+1 -> vrow[(j+1)&1])
//           || stage(quad j+2 -> buf[j&1])
// Data pre-halved at staging; weights pre-halved; +Sum(w/2) folded at the end.
__global__ __launch_bounds__(512, 3)
void m2f_fused_kernel(const float* __restrict__ cls,
                      const float* __restrict__ masks,
                      float* __restrict__ out)
{
    const int k = blockIdx.x;
    const int b = blockIdx.y;
    const int t = threadIdx.x;

    __shared__ __align__(16) float buf[2][QPI][3][SW];    // staged source rows (halved)
    __shared__ __align__(16) float vrow[2][QPI][4][SW];   // vertical lerps (halved)
    __shared__ float2 wts[NQ];
    __shared__ float2 wsum;

    // ---- per-CTA class softmax (halved) ----
    if (t < NQ) {
        const float* p = cls + ((size_t)b * NQ + t) * 3;
        float x0 = p[0], x1 = p[1], x2 = p[2];
        float m  = fmaxf(x0, fmaxf(x1, x2));
        float e0 = __expf(x0 - m), e1 = __expf(x1 - m), e2 = __expf(x2 - m);
        float inv = 0.5f / (e0 + e1 + e2);
        wts[t] = make_float2(e0 * inv, e1 * inv);
    }

    // clamped source rows
    const int r0 = (k == 0)      ? 0        : (k - 1);
    const int r2 = (k == SH - 1) ? (SH - 1) : (k + 1);
    const float* mb = masks + (size_t)b * NQ * SH * SW;
    const size_t qstride = (size_t)SH * SW;

    // staging role: 384 threads, one float4 each -> 4 queries x 3 rows x 128 floats
    const bool stager = (t < 384);
    const int  g  = t >> 5;            // warp id 0..15
    const int  sq = g / 3;             // query within quad (0..3) for stagers
    const int  rr = g % 3;             // row 0..2
    const int  c4 = t & 31;            // float4 index
    const int  stg_row = (rr == 0) ? r0 : ((rr == 1) ? k : r2);
    const float4* pf = reinterpret_cast<const float4*>(
        mb + (size_t)sq * qstride + (size_t)stg_row * SW) + c4;
    const size_t step = qstride;       // 4*qstride floats == qstride float4s

    // vertical role: vp = t>>7, vcol = t&127
    const int vp   = t >> 7;
    const int vcol = t & 127;
    const int ra   = (vp < 2) ? 0 : 1;
    const int rb   = ra + 1;
    const float vf = (vp == 0) ? 0.625f : (vp == 1) ? 0.875f
                   : (vp == 2) ? 0.125f : 0.375f;

    // horizontal role: kx = t&127, row-phase ph = t>>7
    const int kx  = t & 127;
    const int ph  = t >> 7;
    const int kxm = (kx == 0)      ? 0        : kx - 1;
    const int kxp = (kx == SW - 1) ? (SW - 1) : kx + 1;

    // ---- prologue: stage quad 0 ----
    if (stager) {
        float4 v = __ldg(pf);
        v.x *= 0.5f; v.y *= 0.5f; v.z *= 0.5f; v.w *= 0.5f;
        reinterpret_cast<float4*>(&buf[0][sq][rr][0])[c4] = v;
        pf += step;
    }
    __syncthreads();   // wts + buf[0] visible

    // weight sum (halved) by warp 0 — overlaps with prologue vertical below
    if (t < 32) {
        float sx = 0.f, sy = 0.f;
        for (int q = t; q < NQ; q += 32) { sx += wts[q].x; sy += wts[q].y; }
        #pragma unroll
        for (int o = 16; o > 0; o >>= 1) {
            sx += __shfl_down_sync(0xFFFFFFFFu, sx, o);
            sy += __shfl_down_sync(0xFFFFFFFFu, sy, o);
        }
        if (t == 0) wsum = make_float2(sx, sy);
    }

    // ---- prologue: vertical quad 0 -> vrow[0]; stage quad 1 -> buf[1] ----
    {
        float4 v;
        if (stager) v = __ldg(pf);
        #pragma unroll
        for (int e = 0; e < QPI; e++) {
            float a  = buf[0][e][ra][vcol];
            float bb = buf[0][e][rb][vcol];
            vrow[0][e][vp][vcol] = fmaf(vf, bb - a, a);
        }
        if (stager) {
            v.x *= 0.5f; v.y *= 0.5f; v.z *= 0.5f; v.w *= 0.5f;
            reinterpret_cast<float4*>(&buf[1][sq][rr][0])[c4] = v;
            pf += step;
        }
    }
    __syncthreads();

    float acc0[4] = {0.f,0.f,0.f,0.f};
    float acc1[4] = {0.f,0.f,0.f,0.f};

    #pragma unroll 1
    for (int j = 0; j < NIT; j++) {
        const int bs = j & 1;
        const int nb = bs ^ 1;

        // prefetch quad j+2
        float4 vn;
        const bool ds = stager && (j + 2 < NIT);
        if (ds) vn = __ldg(pf);

        // vertical: quad j+1 -> vrow[nb]  (reads buf[nb], staged 2 iters ago)
        if (j + 1 < NIT) {
            #pragma unroll
            for (int e = 0; e < QPI; e++) {
                float a  = buf[nb][e][ra][vcol];
                float bb = buf[nb][e][rb][vcol];
                vrow[nb][e][vp][vcol] = fmaf(vf, bb - a, a);
            }
        }

        // horizontal: quad j from vrow[bs]
        #pragma unroll
        for (int e = 0; e < QPI; e++) {
            const float2 w  = wts[QPI * j + e];
            const float  vL = vrow[bs][e][ph][kxm];
            const float  vM = vrow[bs][e][ph][kx];
            const float  vR = vrow[bs][e][ph][kxp];
            const float  dl = vM - vL;
            const float  dr = vR - vM;

            float t0 = fast_tanh(fmaf(0.625f, dl, vL));
            float t1 = fast_tanh(fmaf(0.875f, dl, vL));
            float t2 = fast_tanh(fmaf(0.125f, dr, vM));
            float t3 = fast_tanh(fmaf(0.375f, dr, vM));

            acc0[0] = fmaf(w.x, t0, acc0[0]);
            acc0[1] = fmaf(w.x, t1, acc0[1]);
            acc0[2] = fmaf(w.x, t2, acc0[2]);
            acc0[3] = fmaf(w.x, t3, acc0[3]);
            acc1[0] = fmaf(w.y, t0, acc1[0]);
            acc1[1] = fmaf(w.y, t1, acc1[1]);
            acc1[2] = fmaf(w.y, t2, acc1[2]);
            acc1[3] = fmaf(w.y, t3, acc1[3]);
        }

        // stage quad j+2 -> buf[bs] (quad j's slot; its last read was iter j-1)
        if (ds) {
            vn.x *= 0.5f; vn.y *= 0.5f; vn.z *= 0.5f; vn.w *= 0.5f;
            reinterpret_cast<float4*>(&buf[bs][sq][rr][0])[c4] = vn;
            pf += step;
        }
        __syncthreads();
    }

    // out[b][c][4k+ph][4kx + 0..3] = acc + Sum(w/2)
    const float2 S = wsum;
    const int y = 4 * k + ph;
    float4 o0 = make_float4(acc0[0] + S.x, acc0[1] + S.x,
                            acc0[2] + S.x, acc0[3] + S.x);
    float4 o1 = make_float4(acc1[0] + S.y, acc1[1] + S.y,
                            acc1[2] + S.y, acc1[3] + S.y);
    const size_t base0 = (((size_t)b * 2 + 0) * OH + y) * OW + 4 * kx;
    const size_t base1 = (((size_t)b * 2 + 1) * OH + y) * OW + 4 * kx;
    *reinterpret_cast<float4*>(out + base0) = o0;
    *reinterpret_cast<float4*>(out + base1) = o1;
}

extern "C" void kernel_launch(void* const* d_in, const int* in_sizes, int n_in,
                              void* d_out, int out_size)
{
    const float* cls   = (const float*)d_in[0];  // [8,100,3]
    const float* masks = (const float*)d_in[1];  // [8,100,128,128]
    float*       out   = (float*)d_out;          // [8,2,512,512]

    dim3 grid(SH, NB);
    dim3 block(512);
    m2f_fused_kernel<<<grid, block>>>(cls, masks, out);
}